// round 5
// baseline (speedup 1.0000x reference)
#include <cuda_runtime.h>
#include <cuda_bf16.h>
#include <mma.h>
#include <math.h>
#include <stdint.h>

using namespace nvcuda;

#define NPART   65536
#define NSTEPS  50
#define HD      128
#define CTXD    128
#define LDA     136
#define THREADS 512
#define P_CTA   128
#define GRID    (NPART / P_CTA)

__device__ float g_te[NSTEPS * HD];            // b1 + emb(t) @ W1[130:162]
__device__ float g_pc1[(size_t)NPART * HD];    // ctx @ W1ctx  (L2-resident)
__device__ float g_cc1[(size_t)NPART * HD];    // ctx @ V1ctx + c1

struct Smem {
    __nv_bfloat16 A[2][P_CTA * LDA];      // [hi/lo] activations (also scr/red alias)
    __nv_bfloat16 B[2][2][HD * LDA];      // [net][hi/lo] weights
    float w1z[2 * HD], v1z[2 * HD], v1t[HD];
    float b2s[HD], c2s[HD];
    float w3s[2 * HD], v3s[2 * HD];
    float zbuf[P_CTA * 2];
    float times_s[NSTEPS + 1], dts[NSTEPS], ss[NSTEPS];
};

__device__ __forceinline__ float tanhf_fast(float x) {
    float e = __expf(2.0f * x);
    return 1.0f - __fdividef(2.0f, e + 1.0f);
}

// 32 fp32 values -> hi/lo bf16 A tiles at row p, cols j0..j0+31
__device__ __forceinline__ void store_split32(Smem* sm, int p, int j0, const float* v) {
#pragma unroll
    for (int c = 0; c < 4; c++) {
        uint32_t uh[4], ul[4];
#pragma unroll
        for (int e = 0; e < 4; e++) {
            float a = v[c * 8 + 2 * e], b = v[c * 8 + 2 * e + 1];
            __nv_bfloat162 th, tl;
            th.x = __float2bfloat16(a);
            th.y = __float2bfloat16(b);
            tl.x = __float2bfloat16(a - __bfloat162float(th.x));
            tl.y = __float2bfloat16(b - __bfloat162float(th.y));
            uh[e] = *(uint32_t*)&th;
            ul[e] = *(uint32_t*)&tl;
        }
        int off = p * LDA + j0 + c * 8;
        *(uint4*)&sm->A[0][off] = make_uint4(uh[0], uh[1], uh[2], uh[3]);
        *(uint4*)&sm->A[1][off] = make_uint4(ul[0], ul[1], ul[2], ul[3]);
    }
}

// weight [128][128] row-major -> hi/lo bf16 tiles (LDA padded)
__device__ __forceinline__ void fill_wsplit(const float* __restrict__ src,
                                            __nv_bfloat16* hi, __nv_bfloat16* lo, int tid) {
    for (int idx = tid; idx < HD * HD; idx += THREADS) {
        int k = idx >> 7, n = idx & 127;
        float x = src[idx];
        __nv_bfloat16 h = __float2bfloat16(x);
        hi[k * LDA + n] = h;
        lo[k * LDA + n] = __float2bfloat16(x - __bfloat162float(h));
    }
}

// MODE 0: raw D (+bias) -> gout global. MODE 1: relu+W3 epilogue. MODE 2: tanh+V3 epilogue.
// Internal __syncthreads after A-frag loads (A region then reused as scr).
template<int MODE>
__device__ __forceinline__ void run_gemm(Smem* sm, int net, int mt, int nh, int lane,
    float* scrw, const float* __restrict__ bias, const float* __restrict__ w3arr,
    float* __restrict__ gout, size_t grow, float& d0, float& d1)
{
    wmma::fragment<wmma::matrix_a, 16, 16, 16, __nv_bfloat16, wmma::row_major> ahi[8], alo[8];
    const __nv_bfloat16* Ahi = sm->A[0] + mt * 16 * LDA;
    const __nv_bfloat16* Alo = sm->A[1] + mt * 16 * LDA;
#pragma unroll
    for (int k = 0; k < 8; k++) {
        wmma::load_matrix_sync(ahi[k], Ahi + k * 16, LDA);
        wmma::load_matrix_sync(alo[k], Alo + k * 16, LDA);
    }
    __syncthreads();   // all A frags register-resident; A region (scr alias) now writable

    const __nv_bfloat16* Bhi = sm->B[net][0];
    const __nv_bfloat16* Blo = sm->B[net][1];
    const int r  = lane >> 1;
    const int cb = (lane & 1) * 8;

#pragma unroll
    for (int nt4 = 0; nt4 < 4; nt4++) {
        int nt = nh * 4 + nt4;
        wmma::fragment<wmma::accumulator, 16, 16, 16, float> acc;
        wmma::fill_fragment(acc, 0.0f);
#pragma unroll
        for (int k = 0; k < 8; k++) {
            wmma::fragment<wmma::matrix_b, 16, 16, 16, __nv_bfloat16, wmma::row_major> bh, bl;
            wmma::load_matrix_sync(bh, Bhi + k * 16 * LDA + nt * 16, LDA);
            wmma::mma_sync(acc, ahi[k], bh, acc);
            wmma::mma_sync(acc, alo[k], bh, acc);
            wmma::load_matrix_sync(bl, Blo + k * 16 * LDA + nt * 16, LDA);
            wmma::mma_sync(acc, ahi[k], bl, acc);
        }
        wmma::store_matrix_sync(scrw, acc, 16, wmma::mem_row_major);
        __syncwarp();

        float4 q0 = *(const float4*)&scrw[r * 16 + cb];
        float4 q1 = *(const float4*)&scrw[r * 16 + cb + 4];
        float x[8] = {q0.x, q0.y, q0.z, q0.w, q1.x, q1.y, q1.z, q1.w};
        int col0 = nh * 64 + nt4 * 16 + cb;
        if (MODE == 0) {
#pragma unroll
            for (int i = 0; i < 8; i++) {
                float v = x[i];
                if (bias) v += __ldg(&bias[col0 + i]);
                gout[grow + (size_t)r * HD + col0 + i] = v;
            }
        } else {
#pragma unroll
            for (int i = 0; i < 8; i++) {
                float xv = x[i] + bias[col0 + i];
                float a = (MODE == 1) ? fmaxf(xv, 0.0f) : tanhf_fast(xv);
                float2 w3 = *(const float2*)&w3arr[2 * (col0 + i)];
                d0 = fmaf(a, w3.x, d0);
                d1 = fmaf(a, w3.y, d1);
            }
        }
        __syncwarp();
    }
}

__global__ void te_kernel(const float* __restrict__ times, const float* __restrict__ freqs,
                          const float* __restrict__ W1, const float* __restrict__ b1)
{
    __shared__ float emb[NSTEPS * 32];
    int tid = threadIdx.x;
    for (int e = tid; e < NSTEPS * 32; e += blockDim.x) {
        int t = e >> 5, i = e & 31;
        float arg = 6.2831853071795864769f * times[t] * freqs[i & 15];
        emb[e] = (i < 16) ? sinf(arg) : cosf(arg);
    }
    __syncthreads();
    for (int e = tid; e < NSTEPS * HD; e += blockDim.x) {
        int t = e >> 7, j = e & 127;
        float a = b1[j];
#pragma unroll
        for (int m = 0; m < 32; m++) a = fmaf(emb[t * 32 + m], W1[(130 + m) * HD + j], a);
        g_te[e] = a;
    }
}

__global__ void __launch_bounds__(THREADS, 1)
sde_kernel(const float* __restrict__ z0, const float* __restrict__ pctx,
           const float* __restrict__ cctx, const float* __restrict__ times,
           const float* __restrict__ xi, const float* __restrict__ freqs,
           const float* __restrict__ log_diff,
           const float* __restrict__ W1, const float* __restrict__ b1,
           const float* __restrict__ W2, const float* __restrict__ b2,
           const float* __restrict__ W3, const float* __restrict__ b3,
           const float* __restrict__ V1, const float* __restrict__ c1,
           const float* __restrict__ V2, const float* __restrict__ c2,
           const float* __restrict__ V3, const float* __restrict__ c3,
           float* __restrict__ traj)
{
    extern __shared__ char raw[];
    Smem* sm = (Smem*)raw;

    const int tid   = threadIdx.x;
    const int wid   = tid >> 5;
    const int lane  = tid & 31;
    const int mt    = wid >> 1;          // m-tile (16 particles)
    const int nh    = wid & 1;           // n half (64 cols)
    const int pb    = tid >> 2;          // build-phase particle
    const int j0b   = (tid & 3) * 32;    // build-phase col block
    const int nBase = blockIdx.x * P_CTA;

    float* scrAll = (float*)sm->A[0];            // aliased scratch (16 KB)
    float* scrw   = scrAll + wid * 256;
    float* red    = scrAll + 4096;               // 512 floats

    // ---- tables & params ----
    for (int i = tid; i <= NSTEPS; i += THREADS) sm->times_s[i] = times[i];
    float gb = log1pf(expf(log_diff[0]));
    for (int i = tid; i < 2 * HD; i += THREADS) {
        sm->w1z[i] = W1[i];
        sm->v1z[i] = V1[i];
        sm->w3s[i] = W3[i];
        sm->v3s[i] = V3[i];
    }
    for (int i = tid; i < HD; i += THREADS) {
        sm->v1t[i] = V1[130 * HD + i];
        sm->b2s[i] = b2[i];
        sm->c2s[i] = c2[i];
    }
    fill_wsplit(W1 + 2 * HD, sm->B[0][0], sm->B[0][1], tid);
    fill_wsplit(V1 + 2 * HD, sm->B[1][0], sm->B[1][1], tid);
    __syncthreads();
    if (tid < NSTEPS) {
        float t_i = sm->times_s[tid];
        float dt  = sm->times_s[tid + 1] - t_i;
        sm->dts[tid] = dt;
        sm->ss[tid]  = gb * (1.0f - t_i) * sqrtf(fmaxf(dt, 1e-12f));
    }
    __syncthreads();

    float du0 = 0.f, du1 = 0.f;
    const size_t grow = (size_t)(nBase + mt * 16) * HD;

    // ---- prologue GEMM 1: g_pc1 = pctx @ W1ctx ----
    {
        float v[32];
        const float* src = pctx + (size_t)(nBase + pb) * CTXD + j0b;
#pragma unroll
        for (int c = 0; c < 8; c++) {
            float4 q = __ldg((const float4*)&src[4 * c]);
            v[4*c] = q.x; v[4*c+1] = q.y; v[4*c+2] = q.z; v[4*c+3] = q.w;
        }
        store_split32(sm, pb, j0b, v);
    }
    __syncthreads();
    run_gemm<0>(sm, 0, mt, nh, lane, scrw, nullptr, nullptr, g_pc1, grow, du0, du1);
    __syncthreads();

    // ---- prologue GEMM 2: g_cc1 = cctx @ V1ctx + c1 ----
    {
        float v[32];
        const float* src = cctx + (size_t)(nBase + pb) * CTXD + j0b;
#pragma unroll
        for (int c = 0; c < 8; c++) {
            float4 q = __ldg((const float4*)&src[4 * c]);
            v[4*c] = q.x; v[4*c+1] = q.y; v[4*c+2] = q.z; v[4*c+3] = q.w;
        }
        store_split32(sm, pb, j0b, v);
    }
    __syncthreads();
    run_gemm<0>(sm, 1, mt, nh, lane, scrw, c1, nullptr, g_cc1, grow, du0, du1);
    __syncthreads();

    // ---- step weights: W2 -> B[0], V2 -> B[1]; z init ----
    fill_wsplit(W2, sm->B[0][0], sm->B[0][1], tid);
    fill_wsplit(V2, sm->B[1][0], sm->B[1][1], tid);
    if (tid < P_CTA) {
        float2 zv = *(const float2*)&z0[(size_t)(nBase + tid) * 2];
        *(float2*)&sm->zbuf[2 * tid] = zv;
        *(float2*)&traj[(size_t)(nBase + tid) * 2] = zv;
    }
    const float bc0 = b3[0] + c3[0];
    const float bc1 = b3[1] + c3[1];
    __syncthreads();

    // ---------------- time loop ----------------
    for (int t = 0; t < NSTEPS; t++) {
        const float t_i = sm->times_s[t];
        const float dt  = sm->dts[t];
        const float s   = sm->ss[t];
        float2 zz = *(const float2*)&sm->zbuf[2 * pb];

        // build h1A = relu(pc1 + z.W1z + te[t])
        {
            float v[32];
            const float* pcs = g_pc1 + (size_t)(nBase + pb) * HD + j0b;
            const float* tes = g_te + t * HD + j0b;
#pragma unroll
            for (int c = 0; c < 8; c++) {
                float4 pc = __ldg((const float4*)&pcs[4 * c]);
                float4 te = __ldg((const float4*)&tes[4 * c]);
                float4 w0 = *(const float4*)&sm->w1z[j0b + 4 * c];
                float4 w1 = *(const float4*)&sm->w1z[HD + j0b + 4 * c];
                v[4*c]   = fmaxf(fmaf(zz.y, w1.x, fmaf(zz.x, w0.x, pc.x + te.x)), 0.f);
                v[4*c+1] = fmaxf(fmaf(zz.y, w1.y, fmaf(zz.x, w0.y, pc.y + te.y)), 0.f);
                v[4*c+2] = fmaxf(fmaf(zz.y, w1.z, fmaf(zz.x, w0.z, pc.z + te.z)), 0.f);
                v[4*c+3] = fmaxf(fmaf(zz.y, w1.w, fmaf(zz.x, w0.w, pc.w + te.w)), 0.f);
            }
            store_split32(sm, pb, j0b, v);
        }
        __syncthreads();

        float d0 = 0.f, d1 = 0.f;
        run_gemm<1>(sm, 0, mt, nh, lane, scrw, sm->b2s, sm->w3s, nullptr, 0, d0, d1);
        __syncthreads();

        // build h1B = tanh(cc1 + z.V1z + t*V1t)
        {
            float v[32];
            const float* ccs = g_cc1 + (size_t)(nBase + pb) * HD + j0b;
#pragma unroll
            for (int c = 0; c < 8; c++) {
                float4 cc = __ldg((const float4*)&ccs[4 * c]);
                float4 u0 = *(const float4*)&sm->v1z[j0b + 4 * c];
                float4 u1 = *(const float4*)&sm->v1z[HD + j0b + 4 * c];
                float4 vt = *(const float4*)&sm->v1t[j0b + 4 * c];
                v[4*c]   = tanhf_fast(fmaf(zz.y, u1.x, fmaf(zz.x, u0.x, fmaf(t_i, vt.x, cc.x))));
                v[4*c+1] = tanhf_fast(fmaf(zz.y, u1.y, fmaf(zz.x, u0.y, fmaf(t_i, vt.y, cc.y))));
                v[4*c+2] = tanhf_fast(fmaf(zz.y, u1.z, fmaf(zz.x, u0.z, fmaf(t_i, vt.z, cc.z))));
                v[4*c+3] = tanhf_fast(fmaf(zz.y, u1.w, fmaf(zz.x, u0.w, fmaf(t_i, vt.w, cc.w))));
            }
            store_split32(sm, pb, j0b, v);
        }
        __syncthreads();

        run_gemm<2>(sm, 1, mt, nh, lane, scrw, sm->c2s, sm->v3s, nullptr, 0, d0, d1);
        __syncthreads();

        // reduce n-halves across warp pairs via red
        d0 += __shfl_xor_sync(0xffffffffu, d0, 1);
        d1 += __shfl_xor_sync(0xffffffffu, d1, 1);
        if ((lane & 1) == 0) {
            int pidx = mt * 16 + (lane >> 1);
            red[pidx * 4 + nh * 2 + 0] = d0;
            red[pidx * 4 + nh * 2 + 1] = d1;
        }
        __syncthreads();

        if (tid < P_CTA) {
            float dr0 = red[tid * 4] + red[tid * 4 + 2] + bc0;
            float dr1 = red[tid * 4 + 1] + red[tid * 4 + 3] + bc1;
            float2 xv = *(const float2*)&xi[((size_t)t * NPART + nBase + tid) * 2];
            float2 zo = *(const float2*)&sm->zbuf[2 * tid];
            float zn0 = fmaf(dr0, dt, zo.x) + xv.x * s;
            float zn1 = fmaf(dr1, dt, zo.y) + xv.y * s;
            *(float2*)&sm->zbuf[2 * tid] = make_float2(zn0, zn1);
            *(float2*)&traj[((size_t)(t + 1) * NPART + nBase + tid) * 2] = make_float2(zn0, zn1);
        }
        __syncthreads();
    }
}

extern "C" void kernel_launch(void* const* d_in, const int* in_sizes, int n_in,
                              void* d_out, int out_size)
{
    (void)in_sizes; (void)n_in; (void)out_size;
    const float* z0       = (const float*)d_in[0];
    const float* pctx     = (const float*)d_in[1];
    const float* cctx     = (const float*)d_in[2];
    const float* times    = (const float*)d_in[3];
    const float* xi       = (const float*)d_in[4];
    const float* freqs    = (const float*)d_in[5];
    const float* log_diff = (const float*)d_in[6];
    const float* W1 = (const float*)d_in[7];
    const float* b1 = (const float*)d_in[8];
    const float* W2 = (const float*)d_in[9];
    const float* b2 = (const float*)d_in[10];
    const float* W3 = (const float*)d_in[11];
    const float* b3 = (const float*)d_in[12];
    const float* V1 = (const float*)d_in[13];
    const float* c1 = (const float*)d_in[14];
    const float* V2 = (const float*)d_in[15];
    const float* c2 = (const float*)d_in[16];
    const float* V3 = (const float*)d_in[17];
    const float* c3 = (const float*)d_in[18];
    float* traj = (float*)d_out;

    te_kernel<<<1, 512>>>(times, freqs, W1, b1);

    cudaFuncSetAttribute(sde_kernel, cudaFuncAttributeMaxDynamicSharedMemorySize,
                         (int)sizeof(Smem));
    sde_kernel<<<GRID, THREADS, sizeof(Smem)>>>(
        z0, pctx, cctx, times, xi, freqs, log_diff,
        W1, b1, W2, b2, W3, b3, V1, c1, V2, c2, V3, c3, traj);
}

// round 6
// speedup vs baseline: 1.5137x; 1.5137x over previous
#include <cuda_runtime.h>
#include <cuda_bf16.h>
#include <mma.h>
#include <math.h>
#include <stdint.h>

using namespace nvcuda;

#define NPART   65536
#define NSTEPS  50
#define HD      128
#define CTXD    128
#define LDA     136
#define THREADS 256
#define P_CTA   128
#define GRID    (NPART / P_CTA)

__device__ float g_te[NSTEPS * HD];            // b1 + emb(t) @ W1[130:162]
__device__ float g_pc1[(size_t)NPART * HD];    // ctx @ W1ctx   (L2-resident)
__device__ float g_cc1[(size_t)NPART * HD];    // ctx @ V1ctx + c1

struct Smem {
    __nv_bfloat16 A[4][P_CTA * LDA];   // slots: [0,1]=netA hi/lo, [2,3]=netB hi/lo (139264 B)
    float scr[8][16 * 32];             // per-warp epilogue scratch (16 KB)
    float red[P_CTA * 16];             // per-particle partial drift [p][warp][2] (8 KB)
    float w1z[2 * HD], v1z[2 * HD], v1t[HD];
    float b2s[HD], c2s[HD];
    float w3s[2 * HD], v3s[2 * HD];
    float zbuf[P_CTA * 2];
    float times_s[NSTEPS + 1], dts[NSTEPS], ss[NSTEPS];
};

__device__ __forceinline__ float tanhf_fast(float x) {
    float e = __expf(2.0f * x);
    return 1.0f - __fdividef(2.0f, e + 1.0f);
}

// 32 fp32 -> hi/lo bf16 at row p, cols j0..j0+31
__device__ __forceinline__ void split_store32(__nv_bfloat16* __restrict__ hi,
                                              __nv_bfloat16* __restrict__ lo,
                                              int p, int j0, const float* v) {
#pragma unroll
    for (int c = 0; c < 4; c++) {
        uint32_t uh[4], ul[4];
#pragma unroll
        for (int e = 0; e < 4; e++) {
            float a = v[c * 8 + 2 * e], b = v[c * 8 + 2 * e + 1];
            __nv_bfloat162 th, tl;
            th.x = __float2bfloat16(a);
            th.y = __float2bfloat16(b);
            tl.x = __float2bfloat16(a - __bfloat162float(th.x));
            tl.y = __float2bfloat16(b - __bfloat162float(th.y));
            uh[e] = *(uint32_t*)&th;
            ul[e] = *(uint32_t*)&tl;
        }
        int off = p * LDA + j0 + c * 8;
        *(uint4*)&hi[off] = make_uint4(uh[0], uh[1], uh[2], uh[3]);
        *(uint4*)&lo[off] = make_uint4(ul[0], ul[1], ul[2], ul[3]);
    }
}

// weight [128][128] row-major -> hi/lo bf16 (LDA padded)
__device__ __forceinline__ void fill_wsplit(const float* __restrict__ src,
                                            __nv_bfloat16* hi, __nv_bfloat16* lo, int tid) {
    for (int idx = tid; idx < HD * HD; idx += THREADS) {
        int k = idx >> 7, n = idx & 127;
        float x = src[idx];
        __nv_bfloat16 h = __float2bfloat16(x);
        hi[k * LDA + n] = h;
        lo[k * LDA + n] = __float2bfloat16(x - __bfloat162float(h));
    }
}

typedef wmma::fragment<wmma::matrix_b, 16, 16, 16, __nv_bfloat16, wmma::row_major> FragB;
typedef wmma::fragment<wmma::matrix_a, 16, 16, 16, __nv_bfloat16, wmma::row_major> FragA;
typedef wmma::fragment<wmma::accumulator, 16, 16, 16, float> FragC;

// load this warp's 32-col slice of a weight (hi/lo) into persistent registers
__device__ __forceinline__ void load_bfrags(FragB (&bh)[8][2], FragB (&bl)[8][2],
                                            const __nv_bfloat16* hi, const __nv_bfloat16* lo, int nq) {
#pragma unroll
    for (int k = 0; k < 8; k++)
#pragma unroll
        for (int n2 = 0; n2 < 2; n2++) {
            int col = (nq * 2 + n2) * 16;
            wmma::load_matrix_sync(bh[k][n2], hi + k * 16 * LDA + col, LDA);
            wmma::load_matrix_sync(bl[k][n2], lo + k * 16 * LDA + col, LDA);
        }
}

// GEMM over all 8 m-tiles (mt pairs for ILP), 3-term hi/lo.
// MODE 0: raw D (+optional addv) -> gout.  MODE 1: relu+W3 -> red.  MODE 2: tanh+V3 -> red.
template<int MODE>
__device__ __forceinline__ void gemm_all(const __nv_bfloat16* __restrict__ Ahi,
                                         const __nv_bfloat16* __restrict__ Alo,
                                         FragB (&bh)[8][2], FragB (&bl)[8][2],
                                         float* scrw, float* red, int wid, int nq, int lane,
                                         const float* __restrict__ bias,
                                         const float* __restrict__ w3arr,
                                         float* __restrict__ gout, int nBase,
                                         const float* __restrict__ addv)
{
    const int r  = lane >> 1;
    const int h  = lane & 1;
    const int col0 = nq * 32 + h * 16;

#pragma unroll
    for (int mp = 0; mp < 4; mp++) {
        FragC acc[2][2];
#pragma unroll
        for (int i = 0; i < 2; i++)
#pragma unroll
            for (int j = 0; j < 2; j++) wmma::fill_fragment(acc[i][j], 0.0f);

#pragma unroll
        for (int k = 0; k < 8; k++) {
            FragA ah0, al0, ah1, al1;
            const __nv_bfloat16* a0 = Ahi + (mp * 2) * 16 * LDA + k * 16;
            const __nv_bfloat16* a1 = Ahi + (mp * 2 + 1) * 16 * LDA + k * 16;
            const __nv_bfloat16* b0 = Alo + (mp * 2) * 16 * LDA + k * 16;
            const __nv_bfloat16* b1 = Alo + (mp * 2 + 1) * 16 * LDA + k * 16;
            wmma::load_matrix_sync(ah0, a0, LDA);
            wmma::load_matrix_sync(ah1, a1, LDA);
            wmma::load_matrix_sync(al0, b0, LDA);
            wmma::load_matrix_sync(al1, b1, LDA);
#pragma unroll
            for (int n2 = 0; n2 < 2; n2++) {
                wmma::mma_sync(acc[0][n2], ah0, bh[k][n2], acc[0][n2]);
                wmma::mma_sync(acc[1][n2], ah1, bh[k][n2], acc[1][n2]);
                wmma::mma_sync(acc[0][n2], al0, bh[k][n2], acc[0][n2]);
                wmma::mma_sync(acc[1][n2], al1, bh[k][n2], acc[1][n2]);
                wmma::mma_sync(acc[0][n2], ah0, bl[k][n2], acc[0][n2]);
                wmma::mma_sync(acc[1][n2], ah1, bl[k][n2], acc[1][n2]);
            }
        }

#pragma unroll
        for (int i = 0; i < 2; i++) {
            int mt = mp * 2 + i;
            wmma::store_matrix_sync(scrw, acc[i][0], 32, wmma::mem_row_major);
            wmma::store_matrix_sync(scrw + 16, acc[i][1], 32, wmma::mem_row_major);
            __syncwarp();
            const float* row = &scrw[r * 32 + h * 16];
            if (MODE == 0) {
                float* orow = gout + (size_t)(nBase + mt * 16 + r) * HD + col0;
#pragma unroll
                for (int q = 0; q < 16; q++) {
                    float v = row[q];
                    if (addv) v += __ldg(&addv[col0 + q]);
                    orow[q] = v;
                }
            } else {
                float d0 = 0.f, d1 = 0.f;
#pragma unroll
                for (int q = 0; q < 16; q++) {
                    float x = row[q] + bias[col0 + q];
                    float a = (MODE == 1) ? fmaxf(x, 0.0f) : tanhf_fast(x);
                    float2 w3 = *(const float2*)&w3arr[2 * (col0 + q)];
                    d0 = fmaf(a, w3.x, d0);
                    d1 = fmaf(a, w3.y, d1);
                }
                d0 += __shfl_xor_sync(0xffffffffu, d0, 1);
                d1 += __shfl_xor_sync(0xffffffffu, d1, 1);
                if (h == 0)
                    *(float2*)&red[(mt * 16 + r) * 16 + wid * 2] = make_float2(d0, d1);
            }
            __syncwarp();
        }
    }
}

__global__ void te_kernel(const float* __restrict__ times, const float* __restrict__ freqs,
                          const float* __restrict__ W1, const float* __restrict__ b1)
{
    __shared__ float emb[NSTEPS * 32];
    int tid = threadIdx.x;
    for (int e = tid; e < NSTEPS * 32; e += blockDim.x) {
        int t = e >> 5, i = e & 31;
        float arg = 6.2831853071795864769f * times[t] * freqs[i & 15];
        emb[e] = (i < 16) ? sinf(arg) : cosf(arg);
    }
    __syncthreads();
    for (int e = tid; e < NSTEPS * HD; e += blockDim.x) {
        int t = e >> 7, j = e & 127;
        float a = b1[j];
#pragma unroll
        for (int m = 0; m < 32; m++) a = fmaf(emb[t * 32 + m], W1[(130 + m) * HD + j], a);
        g_te[e] = a;
    }
}

__global__ void __launch_bounds__(THREADS, 1)
sde_kernel(const float* __restrict__ z0, const float* __restrict__ pctx,
           const float* __restrict__ cctx, const float* __restrict__ times,
           const float* __restrict__ xi, const float* __restrict__ freqs,
           const float* __restrict__ log_diff,
           const float* __restrict__ W1, const float* __restrict__ b1,
           const float* __restrict__ W2, const float* __restrict__ b2,
           const float* __restrict__ W3, const float* __restrict__ b3,
           const float* __restrict__ V1, const float* __restrict__ c1,
           const float* __restrict__ V2, const float* __restrict__ c2,
           const float* __restrict__ V3, const float* __restrict__ c3,
           float* __restrict__ traj)
{
    extern __shared__ char raw[];
    Smem* sm = (Smem*)raw;

    const int tid   = threadIdx.x;
    const int wid   = tid >> 5;
    const int lane  = tid & 31;
    const int net   = wid >> 2;        // 0: drift net (relu/W2), 1: cnf net (tanh/V2)
    const int nq    = wid & 3;         // n-quarter (32 cols)
    const int pb    = tid >> 1;        // build-phase particle
    const int j0b   = (tid & 1) * 64;  // build-phase col range (64 cols)
    const int nBase = blockIdx.x * P_CTA;
    float* scrw = &sm->scr[wid][0];

    // ---- tables & params ----
    for (int i = tid; i <= NSTEPS; i += THREADS) sm->times_s[i] = times[i];
    float gb = log1pf(expf(log_diff[0]));
    for (int i = tid; i < 2 * HD; i += THREADS) {
        sm->w1z[i] = W1[i];
        sm->v1z[i] = V1[i];
        sm->w3s[i] = W3[i];
        sm->v3s[i] = V3[i];
    }
    for (int i = tid; i < HD; i += THREADS) {
        sm->v1t[i] = V1[130 * HD + i];
        sm->b2s[i] = b2[i];
        sm->c2s[i] = c2[i];
    }
    __syncthreads();
    if (tid < NSTEPS) {
        float t_i = sm->times_s[tid];
        float dt  = sm->times_s[tid + 1] - t_i;
        sm->dts[tid] = dt;
        sm->ss[tid]  = gb * (1.0f - t_i) * sqrtf(fmaxf(dt, 1e-12f));
    }

    FragB bh[8][2], bl[8][2];   // persistent weight fragments (this warp's 32 cols, its net)

    // ---- prologue: ctx projections via same GEMM machinery ----
    // stage W1ctx -> slots 0/1, V1ctx -> slots 2/3
    fill_wsplit(W1 + 2 * HD, sm->A[0], sm->A[1], tid);
    fill_wsplit(V1 + 2 * HD, sm->A[2], sm->A[3], tid);
    __syncthreads();
    load_bfrags(bh, bl, sm->A[net * 2], sm->A[net * 2 + 1], nq);
    __syncthreads();

    // stage pctx -> slots 0/1, cctx -> slots 2/3
    {
        const float* srcp = pctx + (size_t)(nBase + pb) * CTXD + j0b;
        const float* srcc = cctx + (size_t)(nBase + pb) * CTXD + j0b;
#pragma unroll
        for (int half = 0; half < 2; half++) {
            float v[32];
#pragma unroll
            for (int c = 0; c < 8; c++) {
                float4 q = __ldg((const float4*)&srcp[half * 32 + 4 * c]);
                v[4*c] = q.x; v[4*c+1] = q.y; v[4*c+2] = q.z; v[4*c+3] = q.w;
            }
            split_store32(sm->A[0], sm->A[1], pb, j0b + half * 32, v);
#pragma unroll
            for (int c = 0; c < 8; c++) {
                float4 q = __ldg((const float4*)&srcc[half * 32 + 4 * c]);
                v[4*c] = q.x; v[4*c+1] = q.y; v[4*c+2] = q.z; v[4*c+3] = q.w;
            }
            split_store32(sm->A[2], sm->A[3], pb, j0b + half * 32, v);
        }
    }
    __syncthreads();
    // net0 warps: pc1 = pctx @ W1ctx -> g_pc1 ; net1 warps: cc1 = cctx @ V1ctx + c1 -> g_cc1
    if (net == 0)
        gemm_all<0>(sm->A[0], sm->A[1], bh, bl, scrw, sm->red, wid, nq, lane,
                    nullptr, nullptr, g_pc1, nBase, nullptr);
    else
        gemm_all<0>(sm->A[2], sm->A[3], bh, bl, scrw, sm->red, wid, nq, lane,
                    nullptr, nullptr, g_cc1, nBase, c1);
    __syncthreads();

    // stage step weights W2 -> 0/1, V2 -> 2/3; load persistent frags
    fill_wsplit(W2, sm->A[0], sm->A[1], tid);
    fill_wsplit(V2, sm->A[2], sm->A[3], tid);
    if (tid < P_CTA) {
        float2 zv = *(const float2*)&z0[(size_t)(nBase + tid) * 2];
        *(float2*)&sm->zbuf[2 * tid] = zv;
        *(float2*)&traj[(size_t)(nBase + tid) * 2] = zv;
    }
    __syncthreads();
    load_bfrags(bh, bl, sm->A[net * 2], sm->A[net * 2 + 1], nq);
    const float bc0 = b3[0] + c3[0];
    const float bc1 = b3[1] + c3[1];
    __syncthreads();

    // ---------------- time loop (3 barriers/step) ----------------
    for (int t = 0; t < NSTEPS; t++) {
        const float t_i = sm->times_s[t];
        const float dt  = sm->dts[t];
        const float s   = sm->ss[t];
        float2 zz = *(const float2*)&sm->zbuf[2 * pb];

        // build h1A -> slots 0/1 and h1B -> slots 2/3 (this thread: particle pb, 64 cols)
        {
            const float* pcs = g_pc1 + (size_t)(nBase + pb) * HD + j0b;
            const float* ccs = g_cc1 + (size_t)(nBase + pb) * HD + j0b;
            const float* tes = g_te + t * HD + j0b;
#pragma unroll
            for (int half = 0; half < 2; half++) {
                float v[32];
                int jo = j0b + half * 32;
#pragma unroll
                for (int c = 0; c < 8; c++) {
                    float4 pc = __ldg((const float4*)&pcs[half * 32 + 4 * c]);
                    float4 te = __ldg((const float4*)&tes[half * 32 + 4 * c]);
                    float4 w0 = *(const float4*)&sm->w1z[jo + 4 * c];
                    float4 w1 = *(const float4*)&sm->w1z[HD + jo + 4 * c];
                    v[4*c]   = fmaxf(fmaf(zz.y, w1.x, fmaf(zz.x, w0.x, pc.x + te.x)), 0.f);
                    v[4*c+1] = fmaxf(fmaf(zz.y, w1.y, fmaf(zz.x, w0.y, pc.y + te.y)), 0.f);
                    v[4*c+2] = fmaxf(fmaf(zz.y, w1.z, fmaf(zz.x, w0.z, pc.z + te.z)), 0.f);
                    v[4*c+3] = fmaxf(fmaf(zz.y, w1.w, fmaf(zz.x, w0.w, pc.w + te.w)), 0.f);
                }
                split_store32(sm->A[0], sm->A[1], pb, jo, v);
#pragma unroll
                for (int c = 0; c < 8; c++) {
                    float4 cc = __ldg((const float4*)&ccs[half * 32 + 4 * c]);
                    float4 u0 = *(const float4*)&sm->v1z[jo + 4 * c];
                    float4 u1 = *(const float4*)&sm->v1z[HD + jo + 4 * c];
                    float4 vt = *(const float4*)&sm->v1t[jo + 4 * c];
                    v[4*c]   = tanhf_fast(fmaf(zz.y, u1.x, fmaf(zz.x, u0.x, fmaf(t_i, vt.x, cc.x))));
                    v[4*c+1] = tanhf_fast(fmaf(zz.y, u1.y, fmaf(zz.x, u0.y, fmaf(t_i, vt.y, cc.y))));
                    v[4*c+2] = tanhf_fast(fmaf(zz.y, u1.z, fmaf(zz.x, u0.z, fmaf(t_i, vt.z, cc.z))));
                    v[4*c+3] = tanhf_fast(fmaf(zz.y, u1.w, fmaf(zz.x, u0.w, fmaf(t_i, vt.w, cc.w))));
                }
                split_store32(sm->A[2], sm->A[3], pb, jo, v);
            }
        }
        __syncthreads();

        // concurrent GEMMs: net0 warps on h1A/W2 (relu/W3), net1 warps on h1B/V2 (tanh/V3)
        if (net == 0)
            gemm_all<1>(sm->A[0], sm->A[1], bh, bl, scrw, sm->red, wid, nq, lane,
                        sm->b2s, sm->w3s, nullptr, nBase, nullptr);
        else
            gemm_all<2>(sm->A[2], sm->A[3], bh, bl, scrw, sm->red, wid, nq, lane,
                        sm->c2s, sm->v3s, nullptr, nBase, nullptr);
        __syncthreads();

        // z update
        if (tid < P_CTA) {
            const float* rp = &sm->red[tid * 16];
            float dr0 = bc0, dr1 = bc1;
#pragma unroll
            for (int w = 0; w < 8; w++) {
                dr0 += rp[2 * w];
                dr1 += rp[2 * w + 1];
            }
            float2 xv = *(const float2*)&xi[((size_t)t * NPART + nBase + tid) * 2];
            float2 zo = *(const float2*)&sm->zbuf[2 * tid];
            float zn0 = fmaf(dr0, dt, zo.x) + xv.x * s;
            float zn1 = fmaf(dr1, dt, zo.y) + xv.y * s;
            *(float2*)&sm->zbuf[2 * tid] = make_float2(zn0, zn1);
            *(float2*)&traj[((size_t)(t + 1) * NPART + nBase + tid) * 2] = make_float2(zn0, zn1);
        }
        __syncthreads();
    }
}

extern "C" void kernel_launch(void* const* d_in, const int* in_sizes, int n_in,
                              void* d_out, int out_size)
{
    (void)in_sizes; (void)n_in; (void)out_size;
    const float* z0       = (const float*)d_in[0];
    const float* pctx     = (const float*)d_in[1];
    const float* cctx     = (const float*)d_in[2];
    const float* times    = (const float*)d_in[3];
    const float* xi       = (const float*)d_in[4];
    const float* freqs    = (const float*)d_in[5];
    const float* log_diff = (const float*)d_in[6];
    const float* W1 = (const float*)d_in[7];
    const float* b1 = (const float*)d_in[8];
    const float* W2 = (const float*)d_in[9];
    const float* b2 = (const float*)d_in[10];
    const float* W3 = (const float*)d_in[11];
    const float* b3 = (const float*)d_in[12];
    const float* V1 = (const float*)d_in[13];
    const float* c1 = (const float*)d_in[14];
    const float* V2 = (const float*)d_in[15];
    const float* c2 = (const float*)d_in[16];
    const float* V3 = (const float*)d_in[17];
    const float* c3 = (const float*)d_in[18];
    float* traj = (float*)d_out;

    te_kernel<<<1, 512>>>(times, freqs, W1, b1);

    cudaFuncSetAttribute(sde_kernel, cudaFuncAttributeMaxDynamicSharedMemorySize,
                         (int)sizeof(Smem));
    sde_kernel<<<GRID, THREADS, sizeof(Smem)>>>(
        z0, pctx, cctx, times, xi, freqs, log_diff,
        W1, b1, W2, b2, W3, b3, V1, c1, V2, c2, V3, c3, traj);
}

// round 7
// speedup vs baseline: 1.7358x; 1.1467x over previous
#include <cuda_runtime.h>
#include <cuda_fp16.h>
#include <math.h>
#include <stdint.h>

#define NPART   65536
#define NSTEPS  50
#define HD      128
#define CTXD    128
#define LDA     136      // fp16 elements per row (272 B) -> conflict-free ldmatrix
#define THREADS 256
#define P_CTA   128
#define GRID    (NPART / P_CTA)

__device__ float g_te[NSTEPS * HD];            // b1 + emb(t) @ W1[130:162]
__device__ float g_pc1[(size_t)NPART * HD];    // ctx @ W1ctx   (L2-resident)
__device__ float g_cc1[(size_t)NPART * HD];    // ctx @ V1ctx + c1

struct Smem {
    __half A[4][P_CTA * LDA];     // h1A_hi, h1A_lo, h1B_hi, h1B_lo   (139264 B)
    __half Wlo[2][HD * LDA];      // W2_lo, V2_lo persistent           (69632 B)
    float red[P_CTA * 8 * 2];     // per-particle partials [p][net*4+nq][2] (8 KB)
    float w1z[2 * HD], v1z[2 * HD], v1t[HD];
    float b2s[HD], c2s[HD];
    float w3s[2 * HD], v3s[2 * HD];
    float zbuf[P_CTA * 2];
    float times_s[NSTEPS + 1], dts[NSTEPS], ss[NSTEPS];
};

__device__ __forceinline__ uint32_t smem_u32(const void* p) {
    uint32_t a;
    asm("{ .reg .u64 t; cvta.to.shared.u64 t, %1; cvt.u32.u64 %0, t; }" : "=r"(a) : "l"(p));
    return a;
}
__device__ __forceinline__ void ldm4(uint32_t* r, uint32_t addr) {
    asm volatile("ldmatrix.sync.aligned.m8n8.x4.shared.b16 {%0,%1,%2,%3}, [%4];"
                 : "=r"(r[0]), "=r"(r[1]), "=r"(r[2]), "=r"(r[3]) : "r"(addr));
}
__device__ __forceinline__ void ldm2t(uint32_t* r, uint32_t addr) {
    asm volatile("ldmatrix.sync.aligned.m8n8.x2.trans.shared.b16 {%0,%1}, [%2];"
                 : "=r"(r[0]), "=r"(r[1]) : "r"(addr));
}
__device__ __forceinline__ void mma16816(float4& c, const uint32_t* a, const uint32_t* b) {
    asm volatile("mma.sync.aligned.m16n8k16.row.col.f32.f16.f16.f32 "
                 "{%0,%1,%2,%3}, {%4,%5,%6,%7}, {%8,%9}, {%0,%1,%2,%3};"
                 : "+f"(c.x), "+f"(c.y), "+f"(c.z), "+f"(c.w)
                 : "r"(a[0]), "r"(a[1]), "r"(a[2]), "r"(a[3]), "r"(b[0]), "r"(b[1]));
}
__device__ __forceinline__ float tanhf_fast(float x) {
    float e = __expf(2.0f * x);
    return 1.0f - __fdividef(2.0f, e + 1.0f);
}

// 32 fp32 -> hi/lo fp16 at row p, cols j0..j0+31
__device__ __forceinline__ void split_store32h(__half* __restrict__ hi, __half* __restrict__ lo,
                                               int p, int j0, const float* v) {
#pragma unroll
    for (int c = 0; c < 4; c++) {
        uint32_t uh[4], ul[4];
#pragma unroll
        for (int e = 0; e < 4; e++) {
            float a = v[c * 8 + 2 * e], b = v[c * 8 + 2 * e + 1];
            __half ha = __float2half_rn(a), hb = __float2half_rn(b);
            __half la = __float2half_rn(a - __half2float(ha));
            __half lb = __float2half_rn(b - __half2float(hb));
            __half2 th; th.x = ha; th.y = hb;
            __half2 tl; tl.x = la; tl.y = lb;
            uh[e] = *(uint32_t*)&th;
            ul[e] = *(uint32_t*)&tl;
        }
        int off = p * LDA + j0 + c * 8;
        *(uint4*)&hi[off] = make_uint4(uh[0], uh[1], uh[2], uh[3]);
        *(uint4*)&lo[off] = make_uint4(ul[0], ul[1], ul[2], ul[3]);
    }
}

// weight [128][128] row-major -> fp16 hi/lo (possibly different buffers)
__device__ __forceinline__ void fill_wsplit(const float* __restrict__ src,
                                            __half* hi, __half* lo, int tid) {
    for (int idx = tid; idx < HD * HD; idx += THREADS) {
        int k = idx >> 7, n = idx & 127;
        float x = src[idx];
        __half h = __float2half_rn(x);
        hi[k * LDA + n] = h;
        lo[k * LDA + n] = __float2half_rn(x - __half2float(h));
    }
}

// load persistent B-hi fragments (this warp's 32 cols): Bh[k][nt][2]
__device__ __forceinline__ void load_bhi(uint32_t (&Bh)[8][4][2], uint32_t hiBase, int nq, int lane) {
    uint32_t bOff = (uint32_t)((lane & 15) * LDA + nq * 32) * 2;
#pragma unroll
    for (int k = 0; k < 8; k++)
#pragma unroll
        for (int nt = 0; nt < 4; nt++)
            ldm2t(Bh[k][nt], hiBase + bOff + (uint32_t)(k * 16 * LDA * 2) + (uint32_t)(nt * 8 * 2));
}

// 3-term GEMM over all 8 m-tiles. MODE 0: D(+addv) -> gout. MODE 1: relu+W3 -> red. MODE 2: tanh+V3 -> red.
template<int MODE>
__device__ __forceinline__ void gemm_all(uint32_t aHi, uint32_t aLo, uint32_t bLo,
    const uint32_t (&Bh)[8][4][2], int nq, int lane,
    const float* __restrict__ biasSm, const float* __restrict__ w3Sm,
    float* __restrict__ red, int redoff,
    float* __restrict__ gout, const float* __restrict__ addv, int nBase)
{
    const uint32_t aOff = (uint32_t)((lane & 15) * LDA + ((lane >> 4) & 1) * 8) * 2;
    const uint32_t bOff = (uint32_t)((lane & 15) * LDA + nq * 32) * 2;
    const int g = lane >> 2;
    const int t = lane & 3;

#pragma unroll 1
    for (int mp = 0; mp < 4; mp++) {
        float4 acc[2][4];
#pragma unroll
        for (int i = 0; i < 2; i++)
#pragma unroll
            for (int nt = 0; nt < 4; nt++) acc[i][nt] = make_float4(0.f, 0.f, 0.f, 0.f);

#pragma unroll
        for (int k = 0; k < 8; k++) {
            uint32_t arow0 = (uint32_t)((mp * 2) * 16 * LDA * 2 + k * 16 * 2);
            uint32_t arow1 = arow0 + (uint32_t)(16 * LDA * 2);
            uint32_t ah0[4], ah1[4], al0[4], al1[4];
            ldm4(ah0, aHi + aOff + arow0);
            ldm4(ah1, aHi + aOff + arow1);
            ldm4(al0, aLo + aOff + arow0);
            ldm4(al1, aLo + aOff + arow1);
            uint32_t bl[4][2];
#pragma unroll
            for (int nt = 0; nt < 4; nt++)
                ldm2t(bl[nt], bLo + bOff + (uint32_t)(k * 16 * LDA * 2 + nt * 8 * 2));
#pragma unroll
            for (int nt = 0; nt < 4; nt++) {
                mma16816(acc[0][nt], ah0, Bh[k][nt]);
                mma16816(acc[1][nt], ah1, Bh[k][nt]);
                mma16816(acc[0][nt], al0, Bh[k][nt]);
                mma16816(acc[1][nt], al1, Bh[k][nt]);
                mma16816(acc[0][nt], ah0, bl[nt]);
                mma16816(acc[1][nt], ah1, bl[nt]);
            }
        }

#pragma unroll
        for (int i = 0; i < 2; i++) {
            int mt = mp * 2 + i;
            if (MODE == 0) {
#pragma unroll
                for (int nt = 0; nt < 4; nt++) {
                    int col0 = nq * 32 + nt * 8 + 2 * t;
                    float a0 = 0.f, a1 = 0.f;
                    if (addv) { a0 = __ldg(&addv[col0]); a1 = __ldg(&addv[col0 + 1]); }
                    float4 c = acc[i][nt];
                    *(float2*)&gout[(size_t)(nBase + mt * 16 + g) * HD + col0]     = make_float2(c.x + a0, c.y + a1);
                    *(float2*)&gout[(size_t)(nBase + mt * 16 + g + 8) * HD + col0] = make_float2(c.z + a0, c.w + a1);
                }
            } else {
                float dg0 = 0.f, dg1 = 0.f, dh0 = 0.f, dh1 = 0.f;
#pragma unroll
                for (int nt = 0; nt < 4; nt++) {
                    int col0 = nq * 32 + nt * 8 + 2 * t;
                    float b0 = biasSm[col0], b1 = biasSm[col0 + 1];
                    float4 c = acc[i][nt];
                    float a0, a1, a2, a3;
                    if (MODE == 1) {
                        a0 = fmaxf(c.x + b0, 0.f); a1 = fmaxf(c.y + b1, 0.f);
                        a2 = fmaxf(c.z + b0, 0.f); a3 = fmaxf(c.w + b1, 0.f);
                    } else {
                        a0 = tanhf_fast(c.x + b0); a1 = tanhf_fast(c.y + b1);
                        a2 = tanhf_fast(c.z + b0); a3 = tanhf_fast(c.w + b1);
                    }
                    float2 w30 = *(const float2*)&w3Sm[2 * col0];
                    float2 w31 = *(const float2*)&w3Sm[2 * (col0 + 1)];
                    dg0 = fmaf(a0, w30.x, fmaf(a1, w31.x, dg0));
                    dg1 = fmaf(a0, w30.y, fmaf(a1, w31.y, dg1));
                    dh0 = fmaf(a2, w30.x, fmaf(a3, w31.x, dh0));
                    dh1 = fmaf(a2, w30.y, fmaf(a3, w31.y, dh1));
                }
#pragma unroll
                for (int off = 1; off < 4; off <<= 1) {
                    dg0 += __shfl_xor_sync(0xffffffffu, dg0, off);
                    dg1 += __shfl_xor_sync(0xffffffffu, dg1, off);
                    dh0 += __shfl_xor_sync(0xffffffffu, dh0, off);
                    dh1 += __shfl_xor_sync(0xffffffffu, dh1, off);
                }
                if (t == 0) {
                    *(float2*)&red[((mt * 16 + g) * 8 + redoff) * 2]     = make_float2(dg0, dg1);
                    *(float2*)&red[((mt * 16 + g + 8) * 8 + redoff) * 2] = make_float2(dh0, dh1);
                }
            }
        }
    }
}

__global__ void te_kernel(const float* __restrict__ times, const float* __restrict__ freqs,
                          const float* __restrict__ W1, const float* __restrict__ b1)
{
    __shared__ float emb[NSTEPS * 32];
    int tid = threadIdx.x;
    for (int e = tid; e < NSTEPS * 32; e += blockDim.x) {
        int t = e >> 5, i = e & 31;
        float arg = 6.2831853071795864769f * times[t] * freqs[i & 15];
        emb[e] = (i < 16) ? sinf(arg) : cosf(arg);
    }
    __syncthreads();
    for (int e = tid; e < NSTEPS * HD; e += blockDim.x) {
        int t = e >> 7, j = e & 127;
        float a = b1[j];
#pragma unroll
        for (int m = 0; m < 32; m++) a = fmaf(emb[t * 32 + m], W1[(130 + m) * HD + j], a);
        g_te[e] = a;
    }
}

__global__ void __launch_bounds__(THREADS, 1)
sde_kernel(const float* __restrict__ z0, const float* __restrict__ pctx,
           const float* __restrict__ cctx, const float* __restrict__ times,
           const float* __restrict__ xi, const float* __restrict__ freqs,
           const float* __restrict__ log_diff,
           const float* __restrict__ W1, const float* __restrict__ b1,
           const float* __restrict__ W2, const float* __restrict__ b2,
           const float* __restrict__ W3, const float* __restrict__ b3,
           const float* __restrict__ V1, const float* __restrict__ c1,
           const float* __restrict__ V2, const float* __restrict__ c2,
           const float* __restrict__ V3, const float* __restrict__ c3,
           float* __restrict__ traj)
{
    extern __shared__ char raw[];
    Smem* sm = (Smem*)raw;

    const int tid   = threadIdx.x;
    const int wid   = tid >> 5;
    const int lane  = tid & 31;
    const int net   = wid >> 2;        // 0: drift (relu/W2/W3), 1: cnf (tanh/V2/V3)
    const int nq    = wid & 3;         // 32-col slice
    const int pb    = tid >> 1;        // build-phase particle
    const int j0b   = (tid & 1) * 64;  // build-phase 64-col range
    const int nBase = blockIdx.x * P_CTA;

    // ---- tables & params ----
    for (int i = tid; i <= NSTEPS; i += THREADS) sm->times_s[i] = times[i];
    float gb = log1pf(expf(log_diff[0]));
    for (int i = tid; i < 2 * HD; i += THREADS) {
        sm->w1z[i] = W1[i];
        sm->v1z[i] = V1[i];
        sm->w3s[i] = W3[i];
        sm->v3s[i] = V3[i];
    }
    for (int i = tid; i < HD; i += THREADS) {
        sm->v1t[i] = V1[130 * HD + i];
        sm->b2s[i] = b2[i];
        sm->c2s[i] = c2[i];
    }
    __syncthreads();
    if (tid < NSTEPS) {
        float t_i = sm->times_s[tid];
        float dt  = sm->times_s[tid + 1] - t_i;
        sm->dts[tid] = dt;
        sm->ss[tid]  = gb * (1.0f - t_i) * sqrtf(fmaxf(dt, 1e-12f));
    }

    const uint32_t a0u = smem_u32(sm->A[0]), a1u = smem_u32(sm->A[1]);
    const uint32_t a2u = smem_u32(sm->A[2]), a3u = smem_u32(sm->A[3]);
    const uint32_t wl0 = smem_u32(sm->Wlo[0]), wl1 = smem_u32(sm->Wlo[1]);
    const uint32_t myAhi = net ? a2u : a0u;
    const uint32_t myAlo = net ? a3u : a1u;
    const uint32_t myBlo = net ? wl1 : wl0;

    uint32_t Bh[8][4][2];   // persistent B-hi fragments

    // ---- prologue: ctx projections ----
    fill_wsplit(W1 + 2 * HD, sm->A[0], sm->Wlo[0], tid);   // W1ctx hi->A0, lo->Wlo0
    fill_wsplit(V1 + 2 * HD, sm->A[2], sm->Wlo[1], tid);   // V1ctx hi->A2, lo->Wlo1
    __syncthreads();
    load_bhi(Bh, net ? a2u : a0u, nq, lane);
    __syncthreads();

    {   // stage pctx -> A0/A1, cctx -> A2/A3
        const float* srcp = pctx + (size_t)(nBase + pb) * CTXD + j0b;
        const float* srcc = cctx + (size_t)(nBase + pb) * CTXD + j0b;
#pragma unroll
        for (int half = 0; half < 2; half++) {
            float v[32];
#pragma unroll
            for (int c = 0; c < 8; c++) {
                float4 q = __ldg((const float4*)&srcp[half * 32 + 4 * c]);
                v[4*c] = q.x; v[4*c+1] = q.y; v[4*c+2] = q.z; v[4*c+3] = q.w;
            }
            split_store32h(sm->A[0], sm->A[1], pb, j0b + half * 32, v);
#pragma unroll
            for (int c = 0; c < 8; c++) {
                float4 q = __ldg((const float4*)&srcc[half * 32 + 4 * c]);
                v[4*c] = q.x; v[4*c+1] = q.y; v[4*c+2] = q.z; v[4*c+3] = q.w;
            }
            split_store32h(sm->A[2], sm->A[3], pb, j0b + half * 32, v);
        }
    }
    __syncthreads();
    if (net == 0)
        gemm_all<0>(a0u, a1u, wl0, Bh, nq, lane, nullptr, nullptr,
                    sm->red, 0, g_pc1, nullptr, nBase);
    else
        gemm_all<0>(a2u, a3u, wl1, Bh, nq, lane, nullptr, nullptr,
                    sm->red, 0, g_cc1, c1, nBase);
    __syncthreads();

    // ---- step weights: W2 hi->A0 lo->Wlo0, V2 hi->A2 lo->Wlo1 ----
    fill_wsplit(W2, sm->A[0], sm->Wlo[0], tid);
    fill_wsplit(V2, sm->A[2], sm->Wlo[1], tid);
    if (tid < P_CTA) {
        float2 zv = *(const float2*)&z0[(size_t)(nBase + tid) * 2];
        *(float2*)&sm->zbuf[2 * tid] = zv;
        *(float2*)&traj[(size_t)(nBase + tid) * 2] = zv;
    }
    __syncthreads();
    load_bhi(Bh, net ? a2u : a0u, nq, lane);
    const float bc0 = b3[0] + c3[0];
    const float bc1 = b3[1] + c3[1];
    __syncthreads();

    // ---------------- time loop (3 barriers/step) ----------------
    for (int t = 0; t < NSTEPS; t++) {
        const float t_i = sm->times_s[t];
        const float dt  = sm->dts[t];
        const float s   = sm->ss[t];
        float2 zz = *(const float2*)&sm->zbuf[2 * pb];

        // build h1A -> A0/A1, h1B -> A2/A3
        {
            const float* pcs = g_pc1 + (size_t)(nBase + pb) * HD + j0b;
            const float* ccs = g_cc1 + (size_t)(nBase + pb) * HD + j0b;
            const float* tes = g_te + t * HD + j0b;
#pragma unroll
            for (int half = 0; half < 2; half++) {
                float v[32];
                int jo = j0b + half * 32;
#pragma unroll
                for (int c = 0; c < 8; c++) {
                    float4 pc = __ldg((const float4*)&pcs[half * 32 + 4 * c]);
                    float4 te = __ldg((const float4*)&tes[half * 32 + 4 * c]);
                    float4 w0 = *(const float4*)&sm->w1z[jo + 4 * c];
                    float4 w1 = *(const float4*)&sm->w1z[HD + jo + 4 * c];
                    v[4*c]   = fmaxf(fmaf(zz.y, w1.x, fmaf(zz.x, w0.x, pc.x + te.x)), 0.f);
                    v[4*c+1] = fmaxf(fmaf(zz.y, w1.y, fmaf(zz.x, w0.y, pc.y + te.y)), 0.f);
                    v[4*c+2] = fmaxf(fmaf(zz.y, w1.z, fmaf(zz.x, w0.z, pc.z + te.z)), 0.f);
                    v[4*c+3] = fmaxf(fmaf(zz.y, w1.w, fmaf(zz.x, w0.w, pc.w + te.w)), 0.f);
                }
                split_store32h(sm->A[0], sm->A[1], pb, jo, v);
#pragma unroll
                for (int c = 0; c < 8; c++) {
                    float4 cc = __ldg((const float4*)&ccs[half * 32 + 4 * c]);
                    float4 u0 = *(const float4*)&sm->v1z[jo + 4 * c];
                    float4 u1 = *(const float4*)&sm->v1z[HD + jo + 4 * c];
                    float4 vt = *(const float4*)&sm->v1t[jo + 4 * c];
                    v[4*c]   = tanhf_fast(fmaf(zz.y, u1.x, fmaf(zz.x, u0.x, fmaf(t_i, vt.x, cc.x))));
                    v[4*c+1] = tanhf_fast(fmaf(zz.y, u1.y, fmaf(zz.x, u0.y, fmaf(t_i, vt.y, cc.y))));
                    v[4*c+2] = tanhf_fast(fmaf(zz.y, u1.z, fmaf(zz.x, u0.z, fmaf(t_i, vt.z, cc.z))));
                    v[4*c+3] = tanhf_fast(fmaf(zz.y, u1.w, fmaf(zz.x, u0.w, fmaf(t_i, vt.w, cc.w))));
                }
                split_store32h(sm->A[2], sm->A[3], pb, jo, v);
            }
        }
        __syncthreads();

        if (net == 0)
            gemm_all<1>(a0u, a1u, wl0, Bh, nq, lane, sm->b2s, sm->w3s,
                        sm->red, nq, nullptr, nullptr, nBase);
        else
            gemm_all<2>(a2u, a3u, wl1, Bh, nq, lane, sm->c2s, sm->v3s,
                        sm->red, 4 + nq, nullptr, nullptr, nBase);
        __syncthreads();

        if (tid < P_CTA) {
            const float* rp = &sm->red[tid * 16];
            float dr0 = bc0, dr1 = bc1;
#pragma unroll
            for (int w = 0; w < 8; w++) {
                dr0 += rp[2 * w];
                dr1 += rp[2 * w + 1];
            }
            float2 xv = *(const float2*)&xi[((size_t)t * NPART + nBase + tid) * 2];
            float2 zo = *(const float2*)&sm->zbuf[2 * tid];
            float zn0 = fmaf(dr0, dt, zo.x) + xv.x * s;
            float zn1 = fmaf(dr1, dt, zo.y) + xv.y * s;
            *(float2*)&sm->zbuf[2 * tid] = make_float2(zn0, zn1);
            *(float2*)&traj[((size_t)(t + 1) * NPART + nBase + tid) * 2] = make_float2(zn0, zn1);
        }
        __syncthreads();
    }
}

extern "C" void kernel_launch(void* const* d_in, const int* in_sizes, int n_in,
                              void* d_out, int out_size)
{
    (void)in_sizes; (void)n_in; (void)out_size;
    const float* z0       = (const float*)d_in[0];
    const float* pctx     = (const float*)d_in[1];
    const float* cctx     = (const float*)d_in[2];
    const float* times    = (const float*)d_in[3];
    const float* xi       = (const float*)d_in[4];
    const float* freqs    = (const float*)d_in[5];
    const float* log_diff = (const float*)d_in[6];
    const float* W1 = (const float*)d_in[7];
    const float* b1 = (const float*)d_in[8];
    const float* W2 = (const float*)d_in[9];
    const float* b2 = (const float*)d_in[10];
    const float* W3 = (const float*)d_in[11];
    const float* b3 = (const float*)d_in[12];
    const float* V1 = (const float*)d_in[13];
    const float* c1 = (const float*)d_in[14];
    const float* V2 = (const float*)d_in[15];
    const float* c2 = (const float*)d_in[16];
    const float* V3 = (const float*)d_in[17];
    const float* c3 = (const float*)d_in[18];
    float* traj = (float*)d_out;

    te_kernel<<<1, 512>>>(times, freqs, W1, b1);

    cudaFuncSetAttribute(sde_kernel, cudaFuncAttributeMaxDynamicSharedMemorySize,
                         (int)sizeof(Smem));
    sde_kernel<<<GRID, THREADS, sizeof(Smem)>>>(
        z0, pctx, cctx, times, xi, freqs, log_diff,
        W1, b1, W2, b2, W3, b3, V1, c1, V2, c2, V3, c3, traj);
}